// round 13
// baseline (speedup 1.0000x reference)
#include <cuda_runtime.h>
#include <cstdint>

// In2MA fused per-window kernel, round 12 resubmit (R12 never ran: infra failure).
// R12 vs R11: big-GEMM weights in __constant__ (LDC = separate const port,
// off the L1 crossbar), big GEMMs retiled 2tok x 8col (halves A-LDS),
// staging phases for big GEMMs removed.

#define P64 68   // pitch for 64-wide rows: 272B
#define P32 36   // pitch for 32-wide rows: 144B
#define WP  68   // weight stage pitch (K=64)
#define WP32 36  // weight stage pitch (K=32)
#define LOG2E 1.4426950408889634f
#define EXSCALE (0.3535533905932738f * LOG2E)   // 8^-0.5 * log2e

typedef unsigned long long u64;

__constant__ float c_wbig[16384];   // [v1 | inner_out | v2 | inter_out], 16KB each
#define WB_V1    0
#define WB_INNER 4096
#define WB_V2    8192
#define WB_INTER 12288

__device__ float g_pos_pan_t[16 * 8 * 64 * 4];   // [j4][h][i][jj], pre-scaled by log2e
__device__ float g_pos_col_t[8 * 8 * 32 * 4];    // [j4][h][i][jj], pre-scaled by log2e

__device__ __forceinline__ u64 ffma2(u64 a, u64 b, u64 c) {
    u64 d;
    asm("fma.rn.f32x2 %0, %1, %2, %3;" : "=l"(d) : "l"(a), "l"(b), "l"(c));
    return d;
}
__device__ __forceinline__ float hadd2(u64 v) {
    float lo, hi;
    asm("mov.b64 {%0, %1}, %2;" : "=f"(lo), "=f"(hi) : "l"(v));
    return lo + hi;
}
__device__ __forceinline__ float ex2(float x) {
    float r;
    asm("ex2.approx.ftz.f32 %0, %1;" : "=f"(r) : "f"(x));
    return r;
}
__device__ __forceinline__ float dot4(float4 a, float4 b) {
    return a.x * b.x + a.y * b.y + a.z * b.z + a.w * b.w;
}

// Stage ROWS x K weight matrix (gmem row-major) into smem with row pitch WPITCH.
template <int ROWS, int K, int WPITCH>
__device__ __forceinline__ void stage_wp(const float* __restrict__ src,
                                         float* __restrict__ dst, int tid) {
    constexpr int C4 = K / 4;
    for (int idx = tid; idx < ROWS * C4; idx += 256) {
        const int r = idx / C4, c = idx % C4;
        reinterpret_cast<float4*>(dst + r * WPITCH)[c] =
            reinterpret_cast<const float4*>(src + r * K)[c];
    }
}

// 64x64 K=64 GEMM with weights in __constant__ (offset wbase, row-major 64x64).
// lane l owns tokens {l, l+32}; warp w owns cols w*8..w*8+7.
// A-LDS: 2 per kk per warp (lane-distinct, conflict-free); W via LDC (const port).
template <int PA, int PO>
__device__ __forceinline__ void gemm64_c(const float* __restrict__ A,
                                         int wbase, float* __restrict__ O, int tid) {
    const int l = tid & 31;
    const int w = tid >> 5;
    const float* __restrict__ cw = c_wbig + wbase + (w * 8) * 64;
    const ulonglong2* __restrict__ a0p = reinterpret_cast<const ulonglong2*>(A + l * PA);
    const ulonglong2* __restrict__ a1p = reinterpret_cast<const ulonglong2*>(A + (l + 32) * PA);
    u64 acc[16];
#pragma unroll
    for (int t = 0; t < 16; ++t) acc[t] = 0ull;
#pragma unroll 4
    for (int kk = 0; kk < 16; ++kk) {
        const ulonglong2 a0 = a0p[kk];
        const ulonglong2 a1 = a1p[kk];
#pragma unroll
        for (int g = 0; g < 8; ++g) {
            const ulonglong2 wv = *reinterpret_cast<const ulonglong2*>(cw + g * 64 + kk * 4);
            acc[g]     = ffma2(a0.x, wv.x, acc[g]);
            acc[g]     = ffma2(a0.y, wv.y, acc[g]);
            acc[8 + g] = ffma2(a1.x, wv.x, acc[8 + g]);
            acc[8 + g] = ffma2(a1.y, wv.y, acc[8 + g]);
        }
    }
    float4 r;
    r.x = hadd2(acc[0]); r.y = hadd2(acc[1]); r.z = hadd2(acc[2]); r.w = hadd2(acc[3]);
    *reinterpret_cast<float4*>(O + l * PO + w * 8) = r;
    r.x = hadd2(acc[4]); r.y = hadd2(acc[5]); r.z = hadd2(acc[6]); r.w = hadd2(acc[7]);
    *reinterpret_cast<float4*>(O + l * PO + w * 8 + 4) = r;
    r.x = hadd2(acc[8]); r.y = hadd2(acc[9]); r.z = hadd2(acc[10]); r.w = hadd2(acc[11]);
    *reinterpret_cast<float4*>(O + (l + 32) * PO + w * 8) = r;
    r.x = hadd2(acc[12]); r.y = hadd2(acc[13]); r.z = hadd2(acc[14]); r.w = hadd2(acc[15]);
    *reinterpret_cast<float4*>(O + (l + 32) * PO + w * 8 + 4) = r;
}

// 64xN=32 GEMM, 4tok x 2col per thread, weights staged in smem (pitch per K).
template <int K, int PA, int PO>
__device__ __forceinline__ void gemm_n32s(const float* __restrict__ A,
                                          const float* __restrict__ sw,
                                          float* __restrict__ O, int tid) {
    constexpr int WPIT = (K == 64) ? WP : WP32;
    const int l = tid & 31;
    const int w = tid >> 5;
    const int tokBase = (w & 1) * 32 + (l & 7);
    const int colBase = (w >> 1) * 8 + (l >> 3);   // + 4g
    u64 acc[8];
#pragma unroll
    for (int t = 0; t < 8; ++t) acc[t] = 0ull;
#pragma unroll 4
    for (int kk = 0; kk < K / 4; ++kk) {
        ulonglong2 a[4];
#pragma unroll
        for (int lt = 0; lt < 4; ++lt)
            a[lt] = reinterpret_cast<const ulonglong2*>(A + (tokBase + lt * 8) * PA)[kk];
#pragma unroll
        for (int g = 0; g < 2; ++g) {
            const ulonglong2 wv = reinterpret_cast<const ulonglong2*>(sw + (colBase + 4 * g) * WPIT)[kk];
#pragma unroll
            for (int lt = 0; lt < 4; ++lt) {
                acc[lt * 2 + g] = ffma2(a[lt].x, wv.x, acc[lt * 2 + g]);
                acc[lt * 2 + g] = ffma2(a[lt].y, wv.y, acc[lt * 2 + g]);
            }
        }
    }
#pragma unroll
    for (int lt = 0; lt < 4; ++lt)
#pragma unroll
        for (int g = 0; g < 2; ++g)
            O[(tokBase + lt * 8) * PO + colBase + 4 * g] = hadd2(acc[lt * 2 + g]);
}

// Direct-LDG 32-col GEMM (k1c only: output occupies the stage region).
template <int K, int PA, int PO>
__device__ __forceinline__ void gemm_direct32(const float* __restrict__ A,
                                              const float* __restrict__ Wg,
                                              float* __restrict__ O, int tid) {
    const int i = tid & 31;
    const int nsub = tid >> 5;
    const ulonglong2* __restrict__ a0 = reinterpret_cast<const ulonglong2*>(A + i * PA);
    const ulonglong2* __restrict__ a1 = reinterpret_cast<const ulonglong2*>(A + (i + 32) * PA);
    u64 acc0[4], acc1[4];
#pragma unroll
    for (int g = 0; g < 4; ++g) { acc0[g] = 0ull; acc1[g] = 0ull; }
#pragma unroll 4
    for (int kk = 0; kk < K / 4; ++kk) {
        const ulonglong2 aa0 = a0[kk];
        const ulonglong2 aa1 = a1[kk];
#pragma unroll
        for (int g = 0; g < 4; ++g) {
            const ulonglong2 w = reinterpret_cast<const ulonglong2*>(Wg + (nsub * 4 + g) * K)[kk];
            acc0[g] = ffma2(aa0.x, w.x, acc0[g]);
            acc0[g] = ffma2(aa0.y, w.y, acc0[g]);
            acc1[g] = ffma2(aa1.x, w.x, acc1[g]);
            acc1[g] = ffma2(aa1.y, w.y, acc1[g]);
        }
    }
    float4 r0, r1;
    r0.x = hadd2(acc0[0]); r0.y = hadd2(acc0[1]);
    r0.z = hadd2(acc0[2]); r0.w = hadd2(acc0[3]);
    r1.x = hadd2(acc1[0]); r1.y = hadd2(acc1[1]);
    r1.z = hadd2(acc1[2]); r1.w = hadd2(acc1[3]);
    *reinterpret_cast<float4*>(O + i * PO + nsub * 4) = r0;
    *reinterpret_cast<float4*>(O + (i + 32) * PO + nsub * 4) = r1;
}

__global__ void transpose_pos_kernel(const float* __restrict__ pi,
                                     const float* __restrict__ pc) {
    const int o = blockIdx.x * 256 + threadIdx.x;
    if (o < 32768) {                        // pan: [j4][h][i][jj] <- pi[h][i][j4*4+jj] * log2e
        const int jj = o & 3, i = (o >> 2) & 63, h = (o >> 8) & 7, j4 = o >> 11;
        g_pos_pan_t[o] = pi[(h * 64 + i) * 64 + j4 * 4 + jj] * LOG2E;
    } else if (o < 32768 + 8192) {          // color
        const int o2 = o - 32768;
        const int jj = o2 & 3, i = (o2 >> 2) & 31, h = (o2 >> 7) & 7, j4 = o2 >> 10;
        g_pos_col_t[o2] = pc[(h * 32 + i) * 32 + j4 * 4 + jj] * LOG2E;
    }
}

extern __shared__ float sm[];

__global__ __launch_bounds__(256, 3) void in2ma_kernel(
    const float* __restrict__ x,            // (4,64,256,256)
    const float* __restrict__ pan_feature,  // (4,32,256,256)
    const float* __restrict__ W_pan_q,      // (32,32)
    const float* __restrict__ W_pan_k,      // (32,32)
    const float* __restrict__ W_k2,         // (32,64)
    const float* __restrict__ W_q1c,        // (32,64)
    const float* __restrict__ W_k1c,        // (32,64)
    float* __restrict__ out)                // (4,64,256,256)
{
    const int tid = threadIdx.x;
    const int blk = blockIdx.x;
    const int b  = blk >> 10;
    const int rem = blk & 1023;
    const int hi = rem >> 5;
    const int wi = rem & 31;

    // shared buffers: 2*64*68 + 4*64*36 = 17920 floats = 71680 B
    float* bufA   = sm;                    // 64xP64 : xf -> cat(pan|color) -> v2 (gated)
    float* bufB   = bufA + 64 * P64;       // 64xP64 : v1 -> inner
    float* s_pan  = bufB + 64 * P64;       // 64xP32 : pan -> q1c
    float* s_panq = s_pan + 64 * P32;      // 64xP32 : pan_q (live to the end)
    float* s_pank = s_panq + 64 * P32;     // 64xP32 : pan_k -> k2
    float* s_k1c  = s_pank + 64 * P32;     // 64xP32 : small-W stage <-> k1c
    float* s_whi  = s_k1c;                 // stage alias

    const size_t baseX = ((size_t)(b * 64) * 256 + hi * 8) * 256 + wi * 8;
    const size_t baseP = ((size_t)(b * 32) * 256 + hi * 8) * 256 + wi * 8;

    // ---- load xf (64ch) and pan (32ch) as float4 rows, token-major in smem;
    //      stage W_pan_q|W_pan_k into s_whi (pitch WP32)
    for (int idx = tid; idx < 1024; idx += 256) {
        const int ch = idx >> 4, tr = (idx >> 1) & 7, hf = idx & 1;
        const float4 v = *reinterpret_cast<const float4*>(
            x + baseX + (size_t)ch * 65536 + tr * 256 + hf * 4);
        const int t = tr * 8 + hf * 4;
        bufA[(t + 0) * P64 + ch] = v.x;
        bufA[(t + 1) * P64 + ch] = v.y;
        bufA[(t + 2) * P64 + ch] = v.z;
        bufA[(t + 3) * P64 + ch] = v.w;
    }
    for (int idx = tid; idx < 512; idx += 256) {
        const int ch = idx >> 4, tr = (idx >> 1) & 7, hf = idx & 1;
        const float4 v = *reinterpret_cast<const float4*>(
            pan_feature + baseP + (size_t)ch * 65536 + tr * 256 + hf * 4);
        const int t = tr * 8 + hf * 4;
        s_pan[(t + 0) * P32 + ch] = v.x;
        s_pan[(t + 1) * P32 + ch] = v.y;
        s_pan[(t + 2) * P32 + ch] = v.z;
        s_pan[(t + 3) * P32 + ch] = v.w;
    }
    stage_wp<32, 32, WP32>(W_pan_q, s_whi, tid);
    stage_wp<32, 32, WP32>(W_pan_k, s_whi + 32 * WP32, tid);
    __syncthreads();

    // ---- pan projections (K=32, N=32)
    gemm_n32s<32, P32, P32>(s_pan, s_whi,             s_panq, tid);
    gemm_n32s<32, P32, P32>(s_pan, s_whi + 32 * WP32, s_pank, tid);
    __syncthreads();

    // ---- v1 = xf @ W_v1^T (const weights) ; stage W_q1c into s_whi same phase
    stage_wp<32, 64, WP>(W_q1c, s_whi, tid);
    gemm64_c<P64, P64>(bufA, WB_V1, bufB, tid);
    __syncthreads();

    // ---- q1c (staged W; reads bufA (xf), writes s_pan; pan raw data dead). Safe.
    gemm_n32s<64, P64, P32>(bufA, s_whi, s_pan, tid);
    __syncthreads();

    // ---- k1c (direct LDG: output occupies s_k1c = s_whi)
    gemm_direct32<64, P64, P32>(bufA, W_k1c, s_k1c, tid);
    __syncthreads();

    // ---- pan attention: warp h, lanes i & i+32 share k/v broadcasts
    {
        const int h = tid >> 5;
        const int i = tid & 31;
        float4 q0 = *reinterpret_cast<const float4*>(s_panq + i * P32 + h * 4);
        float4 q1 = *reinterpret_cast<const float4*>(s_panq + (i + 32) * P32 + h * 4);
        q0.x *= EXSCALE; q0.y *= EXSCALE; q0.z *= EXSCALE; q0.w *= EXSCALE;
        q1.x *= EXSCALE; q1.y *= EXSCALE; q1.z *= EXSCALE; q1.w *= EXSCALE;
        const float4* __restrict__ pt4 = reinterpret_cast<const float4*>(g_pos_pan_t);
        float l0 = 0.f, l1 = 0.f;
        float4 acc0 = make_float4(0.f, 0.f, 0.f, 0.f);
        float4 acc1 = make_float4(0.f, 0.f, 0.f, 0.f);
#pragma unroll 2
        for (int j4 = 0; j4 < 16; ++j4) {
            const float4 p0 = pt4[(j4 * 8 + h) * 64 + i];
            const float4 p1 = pt4[(j4 * 8 + h) * 64 + i + 32];
            const float ps0[4] = {p0.x, p0.y, p0.z, p0.w};
            const float ps1[4] = {p1.x, p1.y, p1.z, p1.w};
#pragma unroll
            for (int jj = 0; jj < 4; ++jj) {
                const int j = j4 * 4 + jj;
                const float4 k4 = *reinterpret_cast<const float4*>(s_pank + j * P32 + h * 4);
                const float4 v  = *reinterpret_cast<const float4*>(bufB + j * P64 + h * 4);
                const float pe0 = ex2(dot4(q0, k4) + ps0[jj]);
                const float pe1 = ex2(dot4(q1, k4) + ps1[jj]);
                l0 += pe0; l1 += pe1;
                acc0.x += pe0 * v.x; acc0.y += pe0 * v.y;
                acc0.z += pe0 * v.z; acc0.w += pe0 * v.w;
                acc1.x += pe1 * v.x; acc1.y += pe1 * v.y;
                acc1.z += pe1 * v.z; acc1.w += pe1 * v.w;
            }
        }
        const float inv0 = 1.f / l0, inv1 = 1.f / l1;
        *reinterpret_cast<float4*>(bufA + i * P64 + h * 4) =
            make_float4(acc0.x * inv0, acc0.y * inv0, acc0.z * inv0, acc0.w * inv0);
        *reinterpret_cast<float4*>(bufA + (i + 32) * P64 + h * 4) =
            make_float4(acc1.x * inv1, acc1.y * inv1, acc1.z * inv1, acc1.w * inv1);
    }

    // ---- color attention: heads=8, seq=32 channels, d=8 in-group tokens
    {
        const int h = tid >> 5, i = tid & 31;
        float q8[8];
#pragma unroll
        for (int d = 0; d < 8; ++d) q8[d] = s_pan[(h * 8 + d) * P32 + i] * EXSCALE;
        const float4* __restrict__ pc4 = reinterpret_cast<const float4*>(g_pos_col_t);
        float l = 0.f;
        float acc8[8] = {0.f, 0.f, 0.f, 0.f, 0.f, 0.f, 0.f, 0.f};
#pragma unroll 2
        for (int j4 = 0; j4 < 8; ++j4) {
            float4 s4 = pc4[(j4 * 8 + h) * 32 + i];         // coalesced over lanes
#pragma unroll
            for (int d = 0; d < 8; ++d) {
                const float4 k4 = *reinterpret_cast<const float4*>(s_k1c + (h * 8 + d) * P32 + j4 * 4);
                s4.x += q8[d] * k4.x; s4.y += q8[d] * k4.y;
                s4.z += q8[d] * k4.z; s4.w += q8[d] * k4.w;
            }
            const float4 pe = make_float4(ex2(s4.x), ex2(s4.y), ex2(s4.z), ex2(s4.w));
            l += pe.x + pe.y + pe.z + pe.w;
#pragma unroll
            for (int d = 0; d < 8; ++d) {
                const float4 v = *reinterpret_cast<const float4*>(bufB + (h * 8 + d) * P64 + 32 + j4 * 4);
                acc8[d] += dot4(pe, v);
            }
        }
        const float inv = 1.f / l;
#pragma unroll
        for (int d = 0; d < 8; ++d) bufA[(h * 8 + d) * P64 + 32 + i] = acc8[d] * inv;
    }
    __syncthreads();   // attn done; s_pan and s_k1c dead -> stage region free

    // ---- inner = cat @ W_inner_out^T (const), bufA -> bufB ; stage W_k2 same phase
    stage_wp<32, 64, WP>(W_k2, s_whi, tid);
    gemm64_c<P64, P64>(bufA, WB_INNER, bufB, tid);
    __syncthreads();

    // ---- v2 (const), bufB -> bufA ; k2 (staged), bufB -> s_pank ; same phase
    gemm64_c<P64, P64>(bufB, WB_V2, bufA, tid);
    gemm_n32s<64, P64, P32>(bufB, s_whi, s_pank, tid);
    __syncthreads();

    // ---- inter attention (cosine gate), scale v2 rows in place
    for (int p = tid; p < 512; p += 256) {
        const int h = p >> 6, j = p & 63;
        const float4 q = *reinterpret_cast<const float4*>(s_panq + j * P32 + h * 4);
        const float4 k = *reinterpret_cast<const float4*>(s_pank + j * P32 + h * 4);
        const float qq = dot4(q, q), kk = dot4(k, k), qk = dot4(q, k);
        const float cosv = qk * rsqrtf(qq * kk);
        float* v = bufA + j * P64 + h * 8;
#pragma unroll
        for (int d = 0; d < 8; ++d) v[d] *= cosv;
    }
    __syncthreads();

    // ---- final projection + un-partition store (const weights)
    {
        const int l = tid & 31;
        const int w = tid >> 5;
        const float* __restrict__ cw = c_wbig + WB_INTER + (w * 8) * 64;
        const ulonglong2* __restrict__ a0p = reinterpret_cast<const ulonglong2*>(bufA + l * P64);
        const ulonglong2* __restrict__ a1p = reinterpret_cast<const ulonglong2*>(bufA + (l + 32) * P64);
        u64 acc[16];
#pragma unroll
        for (int t = 0; t < 16; ++t) acc[t] = 0ull;
#pragma unroll 4
        for (int kk = 0; kk < 16; ++kk) {
            const ulonglong2 a0 = a0p[kk];
            const ulonglong2 a1 = a1p[kk];
#pragma unroll
            for (int g = 0; g < 8; ++g) {
                const ulonglong2 wv = *reinterpret_cast<const ulonglong2*>(cw + g * 64 + kk * 4);
                acc[g]     = ffma2(a0.x, wv.x, acc[g]);
                acc[g]     = ffma2(a0.y, wv.y, acc[g]);
                acc[8 + g] = ffma2(a1.x, wv.x, acc[8 + g]);
                acc[8 + g] = ffma2(a1.y, wv.y, acc[8 + g]);
            }
        }
        const size_t base0 = baseX + (size_t)(l >> 3) * 256 + (l & 7);
        const size_t base1 = base0 + 4 * 256;   // token l+32
#pragma unroll
        for (int g = 0; g < 8; ++g) {
            const int n = w * 8 + g;
            out[base0 + (size_t)n * 65536] = hadd2(acc[g]);
            out[base1 + (size_t)n * 65536] = hadd2(acc[8 + g]);
        }
    }
}

extern "C" void kernel_launch(void* const* d_in, const int* in_sizes, int n_in,
                              void* d_out, int out_size) {
    const float* x           = (const float*)d_in[0];
    const float* pan_feature = (const float*)d_in[1];
    const float* W_pan_q     = (const float*)d_in[2];
    const float* W_pan_k     = (const float*)d_in[3];
    const float* W_v1        = (const float*)d_in[4];
    const float* W_v2        = (const float*)d_in[5];
    const float* W_k2        = (const float*)d_in[6];
    const float* W_q1c       = (const float*)d_in[7];
    const float* W_k1c       = (const float*)d_in[8];
    const float* W_inner_out = (const float*)d_in[9];
    const float* W_inter_out = (const float*)d_in[10];
    const float* pos_inner   = (const float*)d_in[11];
    const float* pos_color   = (const float*)d_in[12];
    float* out = (float*)d_out;

    // Fill constant bank with the four big weight matrices (D2D, capturable).
    cudaMemcpyToSymbolAsync(c_wbig, W_v1,        16384, 0,     cudaMemcpyDeviceToDevice, 0);
    cudaMemcpyToSymbolAsync(c_wbig, W_inner_out, 16384, 16384, cudaMemcpyDeviceToDevice, 0);
    cudaMemcpyToSymbolAsync(c_wbig, W_v2,        16384, 32768, cudaMemcpyDeviceToDevice, 0);
    cudaMemcpyToSymbolAsync(c_wbig, W_inter_out, 16384, 49152, cudaMemcpyDeviceToDevice, 0);

    transpose_pos_kernel<<<160, 256>>>(pos_inner, pos_color);

    const int smem_bytes = (2 * 64 * P64 + 4 * 64 * P32) * (int)sizeof(float);  // 71680
    cudaFuncSetAttribute(in2ma_kernel, cudaFuncAttributeMaxDynamicSharedMemorySize, smem_bytes);
    in2ma_kernel<<<4096, 256, smem_bytes>>>(
        x, pan_feature, W_pan_q, W_pan_k, W_k2, W_q1c, W_k1c, out);
}

// round 15
// speedup vs baseline: 8.2822x; 8.2822x over previous
#include <cuda_runtime.h>
#include <cstdint>

// In2MA fused per-window kernel, round 14 resubmit (R14 never ran: infra failure).
// R14 vs R11: merged pan q/k projection (A loaded once) and merged q1c+k1c
// (A loaded once, register-held outputs across internal sync). All else R11.

#define P64 68   // pitch for 64-wide rows: 272B
#define P32 36   // pitch for 32-wide rows: 144B
#define WP  68   // weight stage pitch (K=64)
#define WP32 36  // weight stage pitch (K=32)
#define LOG2E 1.4426950408889634f
#define EXSCALE (0.3535533905932738f * LOG2E)   // 8^-0.5 * log2e

typedef unsigned long long u64;

__device__ float g_pos_pan_t[16 * 8 * 64 * 4];   // [j4][h][i][jj], pre-scaled by log2e
__device__ float g_pos_col_t[8 * 8 * 32 * 4];    // [j4][h][i][jj], pre-scaled by log2e

__device__ __forceinline__ u64 ffma2(u64 a, u64 b, u64 c) {
    u64 d;
    asm("fma.rn.f32x2 %0, %1, %2, %3;" : "=l"(d) : "l"(a), "l"(b), "l"(c));
    return d;
}
__device__ __forceinline__ float hadd2(u64 v) {
    float lo, hi;
    asm("mov.b64 {%0, %1}, %2;" : "=f"(lo), "=f"(hi) : "l"(v));
    return lo + hi;
}
__device__ __forceinline__ float ex2(float x) {
    float r;
    asm("ex2.approx.ftz.f32 %0, %1;" : "=f"(r) : "f"(x));
    return r;
}
__device__ __forceinline__ float dot4(float4 a, float4 b) {
    return a.x * b.x + a.y * b.y + a.z * b.z + a.w * b.w;
}

// Stage ROWS x K weight matrix (gmem row-major) into smem with row pitch WPITCH.
template <int ROWS, int K, int WPITCH>
__device__ __forceinline__ void stage_wp(const float* __restrict__ src,
                                         float* __restrict__ dst, int tid) {
    constexpr int C4 = K / 4;
    for (int idx = tid; idx < ROWS * C4; idx += 256) {
        const int r = idx / C4, c = idx % C4;
        reinterpret_cast<float4*>(dst + r * WPITCH)[c] =
            reinterpret_cast<const float4*>(src + r * K)[c];
    }
}

// 64x64 K=64 GEMM, 4tok x 4col per thread (R11-verified).
// warp w: tokens (w&1)*32+.., col quad q=w>>1. lane: tk=l&7, cg=l>>3.
// W rows 0..31 in swlo, 32..63 in swhi, pitch WP.
template <int PA, int PO>
__device__ __forceinline__ void gemm64_t4(const float* __restrict__ A,
                                          const float* __restrict__ swlo,
                                          const float* __restrict__ swhi,
                                          float* __restrict__ O, int tid) {
    const int l = tid & 31;
    const int w = tid >> 5;
    const int tokBase = (w & 1) * 32 + (l & 7);
    const int q = w >> 1;
    const float* __restrict__ sw = (q < 2) ? swlo : swhi;
    const int wr0 = (q & 1) * 16 + (l >> 3);   // stage row for g=0 (g adds 4)
    const int colBase = q * 16 + (l >> 3);     // output col for g=0 (g adds 4)
    u64 acc[16];
#pragma unroll
    for (int t = 0; t < 16; ++t) acc[t] = 0ull;
#pragma unroll 4
    for (int kk = 0; kk < 16; ++kk) {
        ulonglong2 a[4];
#pragma unroll
        for (int lt = 0; lt < 4; ++lt)
            a[lt] = reinterpret_cast<const ulonglong2*>(A + (tokBase + lt * 8) * PA)[kk];
#pragma unroll
        for (int g = 0; g < 4; ++g) {
            const ulonglong2 wv = reinterpret_cast<const ulonglong2*>(sw + (wr0 + 4 * g) * WP)[kk];
#pragma unroll
            for (int lt = 0; lt < 4; ++lt) {
                acc[lt * 4 + g] = ffma2(a[lt].x, wv.x, acc[lt * 4 + g]);
                acc[lt * 4 + g] = ffma2(a[lt].y, wv.y, acc[lt * 4 + g]);
            }
        }
    }
#pragma unroll
    for (int lt = 0; lt < 4; ++lt)
#pragma unroll
        for (int g = 0; g < 4; ++g)
            O[(tokBase + lt * 8) * PO + colBase + 4 * g] = hadd2(acc[lt * 4 + g]);
}

// MERGED pan projections: q = pan @ Wq^T, k = pan @ Wk^T (K=32, N=32 each).
// A loaded once per kk for both outputs. 4tok x 2col per output per thread.
__device__ __forceinline__ void gemm_qk32(const float* __restrict__ A,
                                          const float* __restrict__ swq,
                                          const float* __restrict__ swk,
                                          float* __restrict__ Oq,
                                          float* __restrict__ Ok, int tid) {
    const int l = tid & 31;
    const int w = tid >> 5;
    const int tokBase = (w & 1) * 32 + (l & 7);
    const int colBase = (w >> 1) * 8 + (l >> 3);   // + 4g
    u64 aq[8], ak[8];
#pragma unroll
    for (int t = 0; t < 8; ++t) { aq[t] = 0ull; ak[t] = 0ull; }
#pragma unroll
    for (int kk = 0; kk < 8; ++kk) {
        ulonglong2 a[4];
#pragma unroll
        for (int lt = 0; lt < 4; ++lt)
            a[lt] = reinterpret_cast<const ulonglong2*>(A + (tokBase + lt * 8) * P32)[kk];
#pragma unroll
        for (int g = 0; g < 2; ++g) {
            const ulonglong2 wq = reinterpret_cast<const ulonglong2*>(swq + (colBase + 4 * g) * WP32)[kk];
            const ulonglong2 wk = reinterpret_cast<const ulonglong2*>(swk + (colBase + 4 * g) * WP32)[kk];
#pragma unroll
            for (int lt = 0; lt < 4; ++lt) {
                aq[lt * 2 + g] = ffma2(a[lt].x, wq.x, aq[lt * 2 + g]);
                aq[lt * 2 + g] = ffma2(a[lt].y, wq.y, aq[lt * 2 + g]);
                ak[lt * 2 + g] = ffma2(a[lt].x, wk.x, ak[lt * 2 + g]);
                ak[lt * 2 + g] = ffma2(a[lt].y, wk.y, ak[lt * 2 + g]);
            }
        }
    }
#pragma unroll
    for (int lt = 0; lt < 4; ++lt)
#pragma unroll
        for (int g = 0; g < 2; ++g) {
            Oq[(tokBase + lt * 8) * P32 + colBase + 4 * g] = hadd2(aq[lt * 2 + g]);
            Ok[(tokBase + lt * 8) * P32 + colBase + 4 * g] = hadd2(ak[lt * 2 + g]);
        }
}

// MERGED q1c + k1c (K=64, N=32 each): A (xf) loaded once per kk for both.
// q1c weights staged in smem (swq, pitch WP); k1c weights direct LDG (Wk gmem).
// Results held in registers across an internal sync so outputs may overwrite
// the q1c weight-stage region (Ok aliases it).
__device__ __forceinline__ void gemm_q1k1(const float* __restrict__ A,
                                          const float* __restrict__ swq,
                                          const float* __restrict__ Wk,
                                          float* __restrict__ Oq,
                                          float* __restrict__ Ok, int tid) {
    const int l = tid & 31;
    const int w = tid >> 5;
    const int tokBase = (w & 1) * 32 + (l & 7);
    const int colBase = (w >> 1) * 8 + (l >> 3);   // + 4g
    u64 aq[8], ak[8];
#pragma unroll
    for (int t = 0; t < 8; ++t) { aq[t] = 0ull; ak[t] = 0ull; }
#pragma unroll 4
    for (int kk = 0; kk < 16; ++kk) {
        ulonglong2 a[4];
#pragma unroll
        for (int lt = 0; lt < 4; ++lt)
            a[lt] = reinterpret_cast<const ulonglong2*>(A + (tokBase + lt * 8) * P64)[kk];
#pragma unroll
        for (int g = 0; g < 2; ++g) {
            const ulonglong2 wq = reinterpret_cast<const ulonglong2*>(swq + (colBase + 4 * g) * WP)[kk];
            const ulonglong2 wk = reinterpret_cast<const ulonglong2*>(Wk + (colBase + 4 * g) * 64)[kk];
#pragma unroll
            for (int lt = 0; lt < 4; ++lt) {
                aq[lt * 2 + g] = ffma2(a[lt].x, wq.x, aq[lt * 2 + g]);
                aq[lt * 2 + g] = ffma2(a[lt].y, wq.y, aq[lt * 2 + g]);
                ak[lt * 2 + g] = ffma2(a[lt].x, wk.x, ak[lt * 2 + g]);
                ak[lt * 2 + g] = ffma2(a[lt].y, wk.y, ak[lt * 2 + g]);
            }
        }
    }
    float rq[8], rk[8];
#pragma unroll
    for (int t = 0; t < 8; ++t) { rq[t] = hadd2(aq[t]); rk[t] = hadd2(ak[t]); }
    __syncthreads();   // all reads of the q1c weight stage complete before overwrite
#pragma unroll
    for (int lt = 0; lt < 4; ++lt)
#pragma unroll
        for (int g = 0; g < 2; ++g) {
            Oq[(tokBase + lt * 8) * P32 + colBase + 4 * g] = rq[lt * 2 + g];
            Ok[(tokBase + lt * 8) * P32 + colBase + 4 * g] = rk[lt * 2 + g];
        }
}

// 64xN=32 GEMM, 4tok x 2col per thread, weights staged in smem (k2 only).
template <int K, int PA, int PO>
__device__ __forceinline__ void gemm_n32s(const float* __restrict__ A,
                                          const float* __restrict__ sw,
                                          float* __restrict__ O, int tid) {
    constexpr int WPIT = (K == 64) ? WP : WP32;
    const int l = tid & 31;
    const int w = tid >> 5;
    const int tokBase = (w & 1) * 32 + (l & 7);
    const int colBase = (w >> 1) * 8 + (l >> 3);   // + 4g
    u64 acc[8];
#pragma unroll
    for (int t = 0; t < 8; ++t) acc[t] = 0ull;
#pragma unroll 4
    for (int kk = 0; kk < K / 4; ++kk) {
        ulonglong2 a[4];
#pragma unroll
        for (int lt = 0; lt < 4; ++lt)
            a[lt] = reinterpret_cast<const ulonglong2*>(A + (tokBase + lt * 8) * PA)[kk];
#pragma unroll
        for (int g = 0; g < 2; ++g) {
            const ulonglong2 wv = reinterpret_cast<const ulonglong2*>(sw + (colBase + 4 * g) * WPIT)[kk];
#pragma unroll
            for (int lt = 0; lt < 4; ++lt) {
                acc[lt * 2 + g] = ffma2(a[lt].x, wv.x, acc[lt * 2 + g]);
                acc[lt * 2 + g] = ffma2(a[lt].y, wv.y, acc[lt * 2 + g]);
            }
        }
    }
#pragma unroll
    for (int lt = 0; lt < 4; ++lt)
#pragma unroll
        for (int g = 0; g < 2; ++g)
            O[(tokBase + lt * 8) * PO + colBase + 4 * g] = hadd2(acc[lt * 2 + g]);
}

__global__ void transpose_pos_kernel(const float* __restrict__ pi,
                                     const float* __restrict__ pc) {
    const int o = blockIdx.x * 256 + threadIdx.x;
    if (o < 32768) {                        // pan: [j4][h][i][jj] <- pi[h][i][j4*4+jj] * log2e
        const int jj = o & 3, i = (o >> 2) & 63, h = (o >> 8) & 7, j4 = o >> 11;
        g_pos_pan_t[o] = pi[(h * 64 + i) * 64 + j4 * 4 + jj] * LOG2E;
    } else if (o < 32768 + 8192) {          // color
        const int o2 = o - 32768;
        const int jj = o2 & 3, i = (o2 >> 2) & 31, h = (o2 >> 7) & 7, j4 = o2 >> 10;
        g_pos_col_t[o2] = pc[(h * 32 + i) * 32 + j4 * 4 + jj] * LOG2E;
    }
}

extern __shared__ float sm[];

__global__ __launch_bounds__(256, 3) void in2ma_kernel(
    const float* __restrict__ x,            // (4,64,256,256)
    const float* __restrict__ pan_feature,  // (4,32,256,256)
    const float* __restrict__ W_pan_q,      // (32,32)
    const float* __restrict__ W_pan_k,      // (32,32)
    const float* __restrict__ W_v1,         // (64,64)
    const float* __restrict__ W_v2,         // (64,64)
    const float* __restrict__ W_k2,         // (32,64)
    const float* __restrict__ W_q1c,        // (32,64)
    const float* __restrict__ W_k1c,        // (32,64)
    const float* __restrict__ W_inner_out,  // (64,64)
    const float* __restrict__ W_inter_out,  // (64,64)
    float* __restrict__ out)                // (4,64,256,256)
{
    const int tid = threadIdx.x;
    const int blk = blockIdx.x;
    const int b  = blk >> 10;
    const int rem = blk & 1023;
    const int hi = rem >> 5;
    const int wi = rem & 31;

    // shared buffers: 2*64*68 + 4*64*36 = 17920 floats = 71680 B
    float* bufA   = sm;                    // 64xP64 : xf -> cat(pan|color) -> v2 (gated)
    float* bufB   = bufA + 64 * P64;       // 64xP64 : v1 -> inner
    float* s_pan  = bufB + 64 * P64;       // 64xP32 : pan -> Wstage(lo) -> q1c
    float* s_panq = s_pan + 64 * P32;      // 64xP32 : pan_q (live to the end)
    float* s_pank = s_panq + 64 * P32;     // 64xP32 : pan_k -> k2
    float* s_k1c  = s_pank + 64 * P32;     // 64xP32 : Wstage(hi) <-> k1c
    float* s_wlo  = s_pan;                 // stage alias: W rows 0..31
    float* s_whi  = s_k1c;                 // stage alias: W rows 32..63

    const size_t baseX = ((size_t)(b * 64) * 256 + hi * 8) * 256 + wi * 8;
    const size_t baseP = ((size_t)(b * 32) * 256 + hi * 8) * 256 + wi * 8;

    // ---- load xf (64ch) and pan (32ch) as float4 rows, token-major in smem;
    //      stage W_pan_q|W_pan_k into s_whi (pitch WP32)
    for (int idx = tid; idx < 1024; idx += 256) {
        const int ch = idx >> 4, tr = (idx >> 1) & 7, hf = idx & 1;
        const float4 v = *reinterpret_cast<const float4*>(
            x + baseX + (size_t)ch * 65536 + tr * 256 + hf * 4);
        const int t = tr * 8 + hf * 4;
        bufA[(t + 0) * P64 + ch] = v.x;
        bufA[(t + 1) * P64 + ch] = v.y;
        bufA[(t + 2) * P64 + ch] = v.z;
        bufA[(t + 3) * P64 + ch] = v.w;
    }
    for (int idx = tid; idx < 512; idx += 256) {
        const int ch = idx >> 4, tr = (idx >> 1) & 7, hf = idx & 1;
        const float4 v = *reinterpret_cast<const float4*>(
            pan_feature + baseP + (size_t)ch * 65536 + tr * 256 + hf * 4);
        const int t = tr * 8 + hf * 4;
        s_pan[(t + 0) * P32 + ch] = v.x;
        s_pan[(t + 1) * P32 + ch] = v.y;
        s_pan[(t + 2) * P32 + ch] = v.z;
        s_pan[(t + 3) * P32 + ch] = v.w;
    }
    stage_wp<32, 32, WP32>(W_pan_q, s_whi, tid);
    stage_wp<32, 32, WP32>(W_pan_k, s_whi + 32 * WP32, tid);
    __syncthreads();

    // ---- merged pan projections (A loaded once)
    gemm_qk32(s_pan, s_whi, s_whi + 32 * WP32, s_panq, s_pank, tid);
    __syncthreads();   // pan (s_pan) dead now

    // ---- v1 = xf @ W_v1^T  (single pass, split stage)
    stage_wp<32, 64, WP>(W_v1,           s_wlo, tid);
    stage_wp<32, 64, WP>(W_v1 + 32 * 64, s_whi, tid);
    __syncthreads();
    gemm64_t4<P64, P64>(bufA, s_wlo, s_whi, bufB, tid);
    __syncthreads();

    // ---- merged q1c + k1c (A = xf loaded once; q1c staged, k1c direct LDG)
    stage_wp<32, 64, WP>(W_q1c, s_whi, tid);
    __syncthreads();
    gemm_q1k1(bufA, s_whi, W_k1c, s_pan, s_k1c, tid);   // internal sync before stores
    __syncthreads();

    // ---- pan attention: warp h, lanes i & i+32 share k/v broadcasts
    {
        const int h = tid >> 5;
        const int i = tid & 31;
        float4 q0 = *reinterpret_cast<const float4*>(s_panq + i * P32 + h * 4);
        float4 q1 = *reinterpret_cast<const float4*>(s_panq + (i + 32) * P32 + h * 4);
        q0.x *= EXSCALE; q0.y *= EXSCALE; q0.z *= EXSCALE; q0.w *= EXSCALE;
        q1.x *= EXSCALE; q1.y *= EXSCALE; q1.z *= EXSCALE; q1.w *= EXSCALE;
        const float4* __restrict__ pt4 = reinterpret_cast<const float4*>(g_pos_pan_t);
        float l0 = 0.f, l1 = 0.f;
        float4 acc0 = make_float4(0.f, 0.f, 0.f, 0.f);
        float4 acc1 = make_float4(0.f, 0.f, 0.f, 0.f);
#pragma unroll 2
        for (int j4 = 0; j4 < 16; ++j4) {
            const float4 p0 = pt4[(j4 * 8 + h) * 64 + i];
            const float4 p1 = pt4[(j4 * 8 + h) * 64 + i + 32];
            const float ps0[4] = {p0.x, p0.y, p0.z, p0.w};
            const float ps1[4] = {p1.x, p1.y, p1.z, p1.w};
#pragma unroll
            for (int jj = 0; jj < 4; ++jj) {
                const int j = j4 * 4 + jj;
                const float4 k4 = *reinterpret_cast<const float4*>(s_pank + j * P32 + h * 4);
                const float4 v  = *reinterpret_cast<const float4*>(bufB + j * P64 + h * 4);
                const float pe0 = ex2(dot4(q0, k4) + ps0[jj]);
                const float pe1 = ex2(dot4(q1, k4) + ps1[jj]);
                l0 += pe0; l1 += pe1;
                acc0.x += pe0 * v.x; acc0.y += pe0 * v.y;
                acc0.z += pe0 * v.z; acc0.w += pe0 * v.w;
                acc1.x += pe1 * v.x; acc1.y += pe1 * v.y;
                acc1.z += pe1 * v.z; acc1.w += pe1 * v.w;
            }
        }
        const float inv0 = 1.f / l0, inv1 = 1.f / l1;
        *reinterpret_cast<float4*>(bufA + i * P64 + h * 4) =
            make_float4(acc0.x * inv0, acc0.y * inv0, acc0.z * inv0, acc0.w * inv0);
        *reinterpret_cast<float4*>(bufA + (i + 32) * P64 + h * 4) =
            make_float4(acc1.x * inv1, acc1.y * inv1, acc1.z * inv1, acc1.w * inv1);
    }

    // ---- color attention: heads=8, seq=32 channels, d=8 in-group tokens
    {
        const int h = tid >> 5, i = tid & 31;
        float q8[8];
#pragma unroll
        for (int d = 0; d < 8; ++d) q8[d] = s_pan[(h * 8 + d) * P32 + i] * EXSCALE;
        const float4* __restrict__ pc4 = reinterpret_cast<const float4*>(g_pos_col_t);
        float l = 0.f;
        float acc8[8] = {0.f, 0.f, 0.f, 0.f, 0.f, 0.f, 0.f, 0.f};
#pragma unroll 2
        for (int j4 = 0; j4 < 8; ++j4) {
            float4 s4 = pc4[(j4 * 8 + h) * 32 + i];         // coalesced over lanes
#pragma unroll
            for (int d = 0; d < 8; ++d) {
                const float4 k4 = *reinterpret_cast<const float4*>(s_k1c + (h * 8 + d) * P32 + j4 * 4);
                s4.x += q8[d] * k4.x; s4.y += q8[d] * k4.y;
                s4.z += q8[d] * k4.z; s4.w += q8[d] * k4.w;
            }
            const float4 pe = make_float4(ex2(s4.x), ex2(s4.y), ex2(s4.z), ex2(s4.w));
            l += pe.x + pe.y + pe.z + pe.w;
#pragma unroll
            for (int d = 0; d < 8; ++d) {
                const float4 v = *reinterpret_cast<const float4*>(bufB + (h * 8 + d) * P64 + 32 + j4 * 4);
                acc8[d] += dot4(pe, v);
            }
        }
        const float inv = 1.f / l;
#pragma unroll
        for (int d = 0; d < 8; ++d) bufA[(h * 8 + d) * P64 + 32 + i] = acc8[d] * inv;
    }
    __syncthreads();   // attn done; s_pan and s_k1c dead -> stage regions free

    // ---- inner = cat @ W_inner_out^T (single pass), bufA -> bufB
    stage_wp<32, 64, WP>(W_inner_out,           s_wlo, tid);
    stage_wp<32, 64, WP>(W_inner_out + 32 * 64, s_whi, tid);
    __syncthreads();
    gemm64_t4<P64, P64>(bufA, s_wlo, s_whi, bufB, tid);
    __syncthreads();

    // ---- v2 (single pass), bufB -> bufA
    stage_wp<32, 64, WP>(W_v2,           s_wlo, tid);
    stage_wp<32, 64, WP>(W_v2 + 32 * 64, s_whi, tid);
    __syncthreads();
    gemm64_t4<P64, P64>(bufB, s_wlo, s_whi, bufA, tid);
    __syncthreads();

    // ---- k2 (stage in s_whi), bufB -> s_pank (pan_k dead)
    stage_wp<32, 64, WP>(W_k2, s_whi, tid);
    __syncthreads();
    gemm_n32s<64, P64, P32>(bufB, s_whi, s_pank, tid);
    __syncthreads();

    // ---- inter attention (cosine gate), scale v2 rows in place
    for (int p = tid; p < 512; p += 256) {
        const int h = p >> 6, j = p & 63;
        const float4 q = *reinterpret_cast<const float4*>(s_panq + j * P32 + h * 4);
        const float4 k = *reinterpret_cast<const float4*>(s_pank + j * P32 + h * 4);
        const float qq = dot4(q, q), kk = dot4(k, k), qk = dot4(q, k);
        const float cosv = qk * rsqrtf(qq * kk);
        float* v = bufA + j * P64 + h * 8;
#pragma unroll
        for (int d = 0; d < 8; ++d) v[d] *= cosv;
    }
    __syncthreads();

    // ---- final projection + un-partition store (4tok x 4col, split stage)
    stage_wp<32, 64, WP>(W_inter_out,           s_wlo, tid);
    stage_wp<32, 64, WP>(W_inter_out + 32 * 64, s_whi, tid);
    __syncthreads();
    {
        const int l = tid & 31;
        const int w = tid >> 5;
        const int tokBase = (w & 1) * 32 + (l & 7);
        const int q = w >> 1;
        const float* __restrict__ sw = (q < 2) ? s_wlo : s_whi;
        const int wr0 = (q & 1) * 16 + (l >> 3);
        const int colBase = q * 16 + (l >> 3);
        u64 acc[16];
#pragma unroll
        for (int t = 0; t < 16; ++t) acc[t] = 0ull;
#pragma unroll 4
        for (int kk = 0; kk < 16; ++kk) {
            ulonglong2 a[4];
#pragma unroll
            for (int lt = 0; lt < 4; ++lt)
                a[lt] = reinterpret_cast<const ulonglong2*>(bufA + (tokBase + lt * 8) * P64)[kk];
#pragma unroll
            for (int g = 0; g < 4; ++g) {
                const ulonglong2 wv = reinterpret_cast<const ulonglong2*>(sw + (wr0 + 4 * g) * WP)[kk];
#pragma unroll
                for (int lt = 0; lt < 4; ++lt) {
                    acc[lt * 4 + g] = ffma2(a[lt].x, wv.x, acc[lt * 4 + g]);
                    acc[lt * 4 + g] = ffma2(a[lt].y, wv.y, acc[lt * 4 + g]);
                }
            }
        }
#pragma unroll
        for (int lt = 0; lt < 4; ++lt) {
            const int tok = tokBase + lt * 8;
            const size_t baseO = baseX + (size_t)(tok >> 3) * 256 + (tok & 7);
#pragma unroll
            for (int g = 0; g < 4; ++g)
                out[baseO + (size_t)(colBase + 4 * g) * 65536] = hadd2(acc[lt * 4 + g]);
        }
    }
}

extern "C" void kernel_launch(void* const* d_in, const int* in_sizes, int n_in,
                              void* d_out, int out_size) {
    const float* x           = (const float*)d_in[0];
    const float* pan_feature = (const float*)d_in[1];
    const float* W_pan_q     = (const float*)d_in[2];
    const float* W_pan_k     = (const float*)d_in[3];
    const float* W_v1        = (const float*)d_in[4];
    const float* W_v2        = (const float*)d_in[5];
    const float* W_k2        = (const float*)d_in[6];
    const float* W_q1c       = (const float*)d_in[7];
    const float* W_k1c       = (const float*)d_in[8];
    const float* W_inner_out = (const float*)d_in[9];
    const float* W_inter_out = (const float*)d_in[10];
    const float* pos_inner   = (const float*)d_in[11];
    const float* pos_color   = (const float*)d_in[12];
    float* out = (float*)d_out;

    transpose_pos_kernel<<<160, 256>>>(pos_inner, pos_color);

    const int smem_bytes = (2 * 64 * P64 + 4 * 64 * P32) * (int)sizeof(float);  // 71680
    cudaFuncSetAttribute(in2ma_kernel, cudaFuncAttributeMaxDynamicSharedMemorySize, smem_bytes);
    in2ma_kernel<<<4096, 256, smem_bytes>>>(
        x, pan_feature, W_pan_q, W_pan_k, W_v1, W_v2, W_k2, W_q1c, W_k1c,
        W_inner_out, W_inter_out, out);
}